// round 13
// baseline (speedup 1.0000x reference)
#include <cuda_runtime.h>
#include <cuda_bf16.h>
#include <cstdint>
#include <math.h>

// ---------------------------------------------------------------------------
// Problem constants
// ---------------------------------------------------------------------------
#define SEQ      4096
#define HIDDEN   2048
#define NHEADS   8
#define NKVHEADS 4
#define HDIM     256
#define CHUNK    2048
#define QDIM     (NHEADS * HDIM)    // 2048
#define KVDIM    (NKVHEADS * HDIM)  // 1024

// ---------------------------------------------------------------------------
// Scratch (device globals — no allocation allowed)
// ---------------------------------------------------------------------------
__device__ float g_x  [SEQ * HIDDEN];
__device__ float g_q  [CHUNK * QDIM];
__device__ float g_k  [SEQ * KVDIM];
__device__ float g_v  [SEQ * KVDIM];
__device__ float g_ao [CHUNK * QDIM];
__device__ float g_wqT[HIDDEN * QDIM];
__device__ float g_wkT[HIDDEN * KVDIM];
__device__ float g_wvT[HIDDEN * KVDIM];
__device__ float g_woT[QDIM * HIDDEN];

// ---------------------------------------------------------------------------
// PTX helpers (sm_80+-portable only — harness PTX targets plain sm_103,
// so tcgen05/TMEM are unavailable; mma.sync is the tensor path)
// ---------------------------------------------------------------------------
static __device__ __forceinline__ uint32_t s2u(const void* p) {
    uint32_t a;
    asm("{ .reg .u64 t; cvta.to.shared.u64 t, %1; cvt.u32.u64 %0, t; }"
        : "=r"(a) : "l"(p));
    return a;
}

static __device__ __forceinline__ void cp16(uint32_t dst, const void* src) {
    asm volatile("cp.async.cg.shared.global [%0], [%1], 16;"
                 :: "r"(dst), "l"(src) : "memory");
}
#define CP_COMMIT() asm volatile("cp.async.commit_group;" ::: "memory")
#define CP_WAIT0()  asm volatile("cp.async.wait_group 0;" ::: "memory")
#define CP_WAIT1()  asm volatile("cp.async.wait_group 1;" ::: "memory")

// round-to-nearest tf32
static __device__ __forceinline__ float rtf32(float x) {
    uint32_t u = __float_as_uint(x), o;
    asm("cvt.rna.tf32.f32 %0, %1;" : "=r"(o) : "r"(u));
    return __uint_as_float(o);
}

#define MMA_TF32(acc, a0, a1, a2, a3, b0, b1)                                \
    asm volatile(                                                            \
        "mma.sync.aligned.m16n8k8.row.col.f32.tf32.tf32.f32 "                \
        "{%0,%1,%2,%3}, {%4,%5,%6,%7}, {%8,%9}, {%0,%1,%2,%3};"              \
        : "+f"((acc)[0]), "+f"((acc)[1]), "+f"((acc)[2]), "+f"((acc)[3])     \
        : "r"(a0), "r"(a1), "r"(a2), "r"(a3), "r"(b0), "r"(b1))

// ---------------------------------------------------------------------------
// tf32 mma.sync GEMM: C[M,N] = A[M,K](K-major,lda) @ B[N,K](K-major,ldb)^T
// CTA tile 128x256, BK=32, 3-stage cp.async pipeline, 256 threads.
// ---------------------------------------------------------------------------
#define TM 128
#define TN 256
#define TK 32
#define LDSW 36
#define AFL  (128 * LDSW)
#define BFL  (256 * LDSW)
#define STGFL (AFL + BFL)
#define GEMM_SMEM (3 * STGFL * 4)

__global__ __launch_bounds__(256) void gemm_tf32(
    const float* __restrict__ A, const float* __restrict__ B,
    float* __restrict__ C,
    int K, int lda, int ldb, int ldc, int roundC)
{
    const int bm = blockIdx.y * TM;
    const int bn = blockIdx.x * TN;
    const int kt = K / TK;

    A += (size_t)bm * lda;
    B += (size_t)bn * ldb;

    extern __shared__ float smf[];
    const int tid  = threadIdx.x;
    const int w    = tid >> 5, lane = tid & 31;
    const int wm   = w >> 2,   wn   = w & 3;
    const int g    = lane >> 2, t4  = lane & 3;

    const int lr = tid >> 3;
    const int lc = (tid & 7) * 4;

    float acc[4][8][4];
    #pragma unroll
    for (int a1 = 0; a1 < 4; a1++)
        #pragma unroll
        for (int b1 = 0; b1 < 8; b1++)
            #pragma unroll
            for (int c1 = 0; c1 < 4; c1++) acc[a1][b1][c1] = 0.f;

    #define LOAD_STAGE(st, k0)                                                  \
    do {                                                                        \
        float* dA = smf + (st) * STGFL;                                         \
        float* dB = dA + AFL;                                                   \
        _Pragma("unroll")                                                       \
        for (int i = 0; i < 4; i++) {                                           \
            int row = lr + i * 32;                                              \
            cp16(s2u(dA + row * LDSW + lc), A + (size_t)row * lda + (k0) + lc); \
        }                                                                       \
        _Pragma("unroll")                                                       \
        for (int i = 0; i < 8; i++) {                                           \
            int row = lr + i * 32;                                              \
            cp16(s2u(dB + row * LDSW + lc), B + (size_t)row * ldb + (k0) + lc); \
        }                                                                       \
        CP_COMMIT();                                                            \
    } while (0)

    LOAD_STAGE(0, 0);
    if (kt > 1) LOAD_STAGE(1, TK); else CP_COMMIT();

    for (int it = 0; it < kt; it++) {
        CP_WAIT1();
        __syncthreads();

        const int st = it % 3;
        const float* sA = smf + st * STGFL;
        const float* sB = sA + AFL;

        if (it + 2 < kt) { const int s2 = (it + 2) % 3; LOAD_STAGE(s2, (it + 2) * TK); }
        else CP_COMMIT();

        #pragma unroll
        for (int kk = 0; kk < 4; kk++) {
            uint32_t af[4][4], bf[8][2];
            #pragma unroll
            for (int tm = 0; tm < 4; tm++) {
                const float* p = sA + (wm * 64 + tm * 16 + g) * LDSW + kk * 8 + t4;
                af[tm][0] = __float_as_uint(p[0]);
                af[tm][1] = __float_as_uint(p[8 * LDSW]);
                af[tm][2] = __float_as_uint(p[4]);
                af[tm][3] = __float_as_uint(p[8 * LDSW + 4]);
            }
            #pragma unroll
            for (int tn = 0; tn < 8; tn++) {
                const float* p = sB + (wn * 64 + tn * 8 + g) * LDSW + kk * 8 + t4;
                bf[tn][0] = __float_as_uint(p[0]);
                bf[tn][1] = __float_as_uint(p[4]);
            }
            #pragma unroll
            for (int tm = 0; tm < 4; tm++)
                #pragma unroll
                for (int tn = 0; tn < 8; tn++)
                    MMA_TF32(acc[tm][tn], af[tm][0], af[tm][1], af[tm][2],
                             af[tm][3], bf[tn][0], bf[tn][1]);
        }
    }

    #pragma unroll
    for (int tm = 0; tm < 4; tm++) {
        const int row0 = bm + wm * 64 + tm * 16 + g;
        #pragma unroll
        for (int tn = 0; tn < 8; tn++) {
            const int col = bn + wn * 64 + tn * 8 + 2 * t4;
            float2 v0 = make_float2(acc[tm][tn][0], acc[tm][tn][1]);
            float2 v1 = make_float2(acc[tm][tn][2], acc[tm][tn][3]);
            if (roundC) {
                v0.x = rtf32(v0.x); v0.y = rtf32(v0.y);
                v1.x = rtf32(v1.x); v1.y = rtf32(v1.y);
            }
            *(float2*)&C[(size_t)row0 * ldc + col]       = v0;
            *(float2*)&C[(size_t)(row0 + 8) * ldc + col] = v1;
        }
    }
    #undef LOAD_STAGE
}

// ---------------------------------------------------------------------------
// Fused flash attention on mma.sync tf32.
// CTA: 64 q-rows x 1 head, 8 warps = 4(m) x 2(n), 256 threads.
// k-tile = 64 keys. Online softmax; cross-warp state in smem (double-buffered).
// ---------------------------------------------------------------------------
#define FQ  64
#define FK  64
#define QLD 260   // ≡4 (mod 32): A/B fragment pattern conflict-free
#define KLD 260
#define VLD 264   // ≡8 (mod 32): V B-fragment pattern conflict-free
#define PLD 68
#define FA_SMEM ((FQ*QLD + FK*KLD + FK*VLD + FQ*PLD + 4*128) * 4)

__global__ __launch_bounds__(256) void flash_mma(
    const float* __restrict__ Qg, const float* __restrict__ Kg,
    const float* __restrict__ Vg, float* __restrict__ Og)
{
    const int qt  = (int)(gridDim.x - 1 - blockIdx.x);   // longest-first
    const int h   = blockIdx.y;
    const int q0  = qt * FQ;
    const int kvh = h >> 1;

    extern __shared__ float sm[];
    float* Qs  = sm;
    float* Ks  = Qs + FQ * QLD;
    float* Vs  = Ks + FK * KLD;
    float* Ps  = Vs + FK * VLD;
    float* pmx = Ps + FQ * PLD;    // [2][64]
    float* psm = pmx + 128;        // [2][64]
    float* sM  = psm + 128;        // [2][64] double-buffered
    float* sL  = sM + 128;         // [2][64]

    const int tid  = threadIdx.x;
    const int w    = tid >> 5, lane = tid & 31;
    const int wm   = w >> 1,   wn   = w & 1;       // 4(m) x 2(n)
    const int g    = lane >> 2, t4  = lane & 3;
    const int r0   = wm * 16 + g;                   // local q rows r0, r0+8

    // --- prologue loads: group {Q, K0}, group {V0} ---
    #pragma unroll
    for (int i = 0; i < 16; i++) {
        int idx = tid + i * 256;
        int r = idx >> 6, c = (idx & 63) * 4;
        cp16(s2u(Qs + r * QLD + c), Qg + (size_t)(q0 + r) * QDIM + h * HDIM + c);
    }
    #pragma unroll
    for (int i = 0; i < 16; i++) {
        int idx = tid + i * 256;
        int r = idx >> 6, c = (idx & 63) * 4;
        cp16(s2u(Ks + r * KLD + c), Kg + (size_t)r * KVDIM + kvh * HDIM + c);
    }
    CP_COMMIT();
    #pragma unroll
    for (int i = 0; i < 16; i++) {
        int idx = tid + i * 256;
        int r = idx >> 6, c = (idx & 63) * 4;
        cp16(s2u(Vs + r * VLD + c), Vg + (size_t)r * KVDIM + kvh * HDIM + c);
    }
    CP_COMMIT();

    if (tid < 64) {
        sM[tid] = -1e30f; sL[tid] = 0.f;
        sM[64 + tid] = -1e30f; sL[64 + tid] = 0.f;
    }

    float o[16][4];
    #pragma unroll
    for (int i = 0; i < 16; i++)
        #pragma unroll
        for (int j = 0; j < 4; j++) o[i][j] = 0.f;

    const int ntiles = (CHUNK + q0) / FK + 1;
    const int qpos0  = CHUNK + q0 + r0;
    const int qpos1  = qpos0 + 8;
    int par = 0;

    for (int kt = 0; kt < ntiles; kt++) {
        const int k0 = kt * FK;
        CP_WAIT1();            // K_kt (older group) ready; V_kt may be in flight
        __syncthreads();

        // ---- S = Q @ K^T (rows r0,r0+8; cols wn*32 + tn*8 + 2t4 + {0,1}) ----
        float s[4][4];
        #pragma unroll
        for (int tn = 0; tn < 4; tn++)
            #pragma unroll
            for (int c = 0; c < 4; c++) s[tn][c] = 0.f;

        #pragma unroll 8
        for (int kk = 0; kk < 32; kk++) {
            uint32_t a0, a1, a2, a3;
            const float* pq = Qs + r0 * QLD + kk * 8 + t4;
            a0 = __float_as_uint(pq[0]);
            a1 = __float_as_uint(pq[8 * QLD]);
            a2 = __float_as_uint(pq[4]);
            a3 = __float_as_uint(pq[8 * QLD + 4]);
            #pragma unroll
            for (int tn = 0; tn < 4; tn++) {
                const float* pk = Ks + (wn * 32 + tn * 8 + g) * KLD + kk * 8 + t4;
                uint32_t b0 = __float_as_uint(pk[0]);
                uint32_t b1 = __float_as_uint(pk[4]);
                MMA_TF32(s[tn], a0, a1, a2, a3, b0, b1);
            }
        }

        // ---- softcap + mask + partial row max ----
        float mx0 = -1e30f, mx1 = -1e30f;
        #pragma unroll
        for (int tn = 0; tn < 4; tn++) {
            const int colb = k0 + wn * 32 + tn * 8 + 2 * t4;
            #pragma unroll
            for (int c = 0; c < 4; c++) {
                const int col = colb + (c & 1);
                // 50*tanh(s*0.0625/50) = 50*(e^{2z}-1)/(e^{2z}+1), z = s*0.00125
                float t = __expf(s[tn][c] * 0.0025f);
                float l = 50.f * __fdividef(t - 1.f, t + 1.f);
                const int qp = (c < 2) ? qpos0 : qpos1;
                s[tn][c] = (col <= qp) ? l : -1e30f;
                if (c < 2) mx0 = fmaxf(mx0, s[tn][c]);
                else       mx1 = fmaxf(mx1, s[tn][c]);
            }
        }
        mx0 = fmaxf(mx0, __shfl_xor_sync(~0u, mx0, 1));
        mx0 = fmaxf(mx0, __shfl_xor_sync(~0u, mx0, 2));
        mx1 = fmaxf(mx1, __shfl_xor_sync(~0u, mx1, 1));
        mx1 = fmaxf(mx1, __shfl_xor_sync(~0u, mx1, 2));
        if (t4 == 0) { pmx[wn * 64 + r0] = mx0; pmx[wn * 64 + r0 + 8] = mx1; }
        __syncthreads();   // (A)

        // prefetch K_{kt+1}: Ks free (all warps past S)
        if (kt + 1 < ntiles) {
            const int kn0 = k0 + FK;
            #pragma unroll
            for (int i = 0; i < 16; i++) {
                int idx = tid + i * 256;
                int r = idx >> 6, c = (idx & 63) * 4;
                cp16(s2u(Ks + r * KLD + c),
                     Kg + (size_t)(kn0 + r) * KVDIM + kvh * HDIM + c);
            }
            CP_COMMIT();
        }

        // ---- online softmax: new max, exp, partial sums, P to smem ----
        const float m0old = sM[par * 64 + r0];
        const float m1old = sM[par * 64 + r0 + 8];
        const float m0 = fmaxf(m0old, fmaxf(pmx[r0],     pmx[64 + r0]));
        const float m1 = fmaxf(m1old, fmaxf(pmx[r0 + 8], pmx[64 + r0 + 8]));
        const float corr0 = __expf(m0old - m0);
        const float corr1 = __expf(m1old - m1);

        float sum0 = 0.f, sum1 = 0.f;
        #pragma unroll
        for (int tn = 0; tn < 4; tn++) {
            float p0 = __expf(s[tn][0] - m0);
            float p1 = __expf(s[tn][1] - m0);
            float p2 = __expf(s[tn][2] - m1);
            float p3 = __expf(s[tn][3] - m1);
            sum0 += p0 + p1;
            sum1 += p2 + p3;
            const int colL = wn * 32 + tn * 8 + 2 * t4;
            *(float2*)&Ps[r0 * PLD + colL]       = make_float2(rtf32(p0), rtf32(p1));
            *(float2*)&Ps[(r0 + 8) * PLD + colL] = make_float2(rtf32(p2), rtf32(p3));
        }
        sum0 += __shfl_xor_sync(~0u, sum0, 1);
        sum0 += __shfl_xor_sync(~0u, sum0, 2);
        sum1 += __shfl_xor_sync(~0u, sum1, 1);
        sum1 += __shfl_xor_sync(~0u, sum1, 2);
        if (t4 == 0) { psm[wn * 64 + r0] = sum0; psm[wn * 64 + r0 + 8] = sum1; }

        // rescale O accumulators
        #pragma unroll
        for (int tn = 0; tn < 16; tn++) {
            o[tn][0] *= corr0; o[tn][1] *= corr0;
            o[tn][2] *= corr1; o[tn][3] *= corr1;
        }
        __syncthreads();   // (B): Ps + psm visible; K prefetch already issued

        // state update (one writer per row) into the other parity buffer
        if (wn == 0 && t4 == 0) {
            sL[(1 - par) * 64 + r0] =
                sL[par * 64 + r0] * corr0 + psm[r0] + psm[64 + r0];
            sM[(1 - par) * 64 + r0] = m0;
            sL[(1 - par) * 64 + r0 + 8] =
                sL[par * 64 + r0 + 8] * corr1 + psm[r0 + 8] + psm[64 + r0 + 8];
            sM[(1 - par) * 64 + r0 + 8] = m1;
        }

        // wait V_kt (all-but-newest: K_{kt+1} may still fly)
        if (kt + 1 < ntiles) CP_WAIT1(); else CP_WAIT0();

        // ---- O += P @ V  (n = d: wn*128 + tn*8; k = 64 keys) ----
        #pragma unroll
        for (int k8 = 0; k8 < 8; k8++) {
            uint32_t a0, a1, a2, a3;
            const float* pp = Ps + r0 * PLD + k8 * 8 + t4;
            a0 = __float_as_uint(pp[0]);
            a1 = __float_as_uint(pp[8 * PLD]);
            a2 = __float_as_uint(pp[4]);
            a3 = __float_as_uint(pp[8 * PLD + 4]);
            #pragma unroll
            for (int tn = 0; tn < 16; tn++) {
                const float* pv = Vs + (k8 * 8 + t4) * VLD + wn * 128 + tn * 8 + g;
                uint32_t b0 = __float_as_uint(pv[0]);
                uint32_t b1 = __float_as_uint(pv[4 * VLD]);
                MMA_TF32(o[tn], a0, a1, a2, a3, b0, b1);
            }
        }
        __syncthreads();   // (C): Vs free

        // prefetch V_{kt+1}
        if (kt + 1 < ntiles) {
            const int kn0 = k0 + FK;
            #pragma unroll
            for (int i = 0; i < 16; i++) {
                int idx = tid + i * 256;
                int r = idx >> 6, c = (idx & 63) * 4;
                cp16(s2u(Vs + r * VLD + c),
                     Vg + (size_t)(kn0 + r) * KVDIM + kvh * HDIM + c);
            }
            CP_COMMIT();
        }
        par ^= 1;
    }

    // ---- epilogue: O /= l, tf32-round, store ----
    const float linv0 = __fdividef(1.f, sL[par * 64 + r0]);
    const float linv1 = __fdividef(1.f, sL[par * 64 + r0 + 8]);
    #pragma unroll
    for (int tn = 0; tn < 16; tn++) {
        const int col = h * HDIM + wn * 128 + tn * 8 + 2 * t4;
        *(float2*)&Og[(size_t)(q0 + r0) * QDIM + col] =
            make_float2(rtf32(o[tn][0] * linv0), rtf32(o[tn][1] * linv0));
        *(float2*)&Og[(size_t)(q0 + r0 + 8) * QDIM + col] =
            make_float2(rtf32(o[tn][2] * linv1), rtf32(o[tn][3] * linv1));
    }
}

// ---------------------------------------------------------------------------
// 32x32 tiled transpose with tf32 rounding
// ---------------------------------------------------------------------------
__global__ __launch_bounds__(256) void transposeK(
    const float* __restrict__ in, float* __restrict__ out,
    int ldin, int ldout)
{
    __shared__ float t[32][33];
    const int c0 = blockIdx.x * 32, r0 = blockIdx.y * 32;
    const int tx = threadIdx.x, ty = threadIdx.y;
    #pragma unroll
    for (int i = ty; i < 32; i += 8)
        t[i][tx] = in[(size_t)(r0 + i) * ldin + c0 + tx];
    __syncthreads();
    #pragma unroll
    for (int i = ty; i < 32; i += 8)
        out[(size_t)(c0 + i) * ldout + r0 + tx] = rtf32(t[tx][i]);
}

// ---------------------------------------------------------------------------
// Elementwise tf32 round
// ---------------------------------------------------------------------------
__global__ __launch_bounds__(256) void round_x(
    const float4* __restrict__ in, float4* __restrict__ out)
{
    int i = blockIdx.x * 256 + threadIdx.x;
    float4 v = in[i];
    v.x = rtf32(v.x); v.y = rtf32(v.y); v.z = rtf32(v.z); v.w = rtf32(v.w);
    out[i] = v;
}

// ---------------------------------------------------------------------------
// RMSNorm (+ optional RoPE), head_dim = 256, in place, tf32-rounded output
// ---------------------------------------------------------------------------
__global__ __launch_bounds__(128) void norm_rope(
    float* __restrict__ buf, const float* __restrict__ w,
    const float* __restrict__ cosb, const float* __restrict__ sinb,
    int nheads, int pos_off, int use_rope)
{
    const int tok = blockIdx.x;
    const int h   = blockIdx.y;
    float* x = buf + ((size_t)tok * nheads + h) * HDIM;
    const int i = threadIdx.x;

    float x1 = x[i];
    float x2 = x[i + 128];
    float ss = x1 * x1 + x2 * x2;
    #pragma unroll
    for (int off = 16; off > 0; off >>= 1)
        ss += __shfl_xor_sync(0xffffffffu, ss, off);
    __shared__ float wsum[4];
    if ((i & 31) == 0) wsum[i >> 5] = ss;
    __syncthreads();
    float tot = wsum[0] + wsum[1] + wsum[2] + wsum[3];

    float scale = rsqrtf(tot * (1.0f / 256.0f) + 1e-6f);
    float xn1 = x1 * scale * (1.0f + w[i]);
    float xn2 = x2 * scale * (1.0f + w[i + 128]);

    if (use_rope) {
        const size_t p = (size_t)(pos_off + tok) * HDIM;
        float c1 = cosb[p + i],       s1 = sinb[p + i];
        float c2 = cosb[p + i + 128], s2 = sinb[p + i + 128];
        x[i]       = rtf32(xn1 * c1 - xn2 * s1);
        x[i + 128] = rtf32(xn2 * c2 + xn1 * s2);
    } else {
        x[i]       = rtf32(xn1);
        x[i + 128] = rtf32(xn2);
    }
}

// ---------------------------------------------------------------------------
// Launch
// ---------------------------------------------------------------------------
extern "C" void kernel_launch(void* const* d_in, const int* in_sizes, int n_in,
                              void* d_out, int out_size)
{
    const float* X    = (const float*)d_in[0];
    const float* cosb = (const float*)d_in[1];
    const float* sinb = (const float*)d_in[2];
    const float* wq   = (const float*)d_in[4];
    const float* wk   = (const float*)d_in[5];
    const float* wv   = (const float*)d_in[6];
    const float* wo   = (const float*)d_in[7];
    const float* qn   = (const float*)d_in[8];
    const float* kn   = (const float*)d_in[9];
    const float* vn   = (const float*)d_in[10];
    float* out = (float*)d_out;

    float *xb, *qb, *kb, *vb, *ab, *wqT, *wkT, *wvT, *woT;
    cudaGetSymbolAddress((void**)&xb,  g_x);
    cudaGetSymbolAddress((void**)&qb,  g_q);
    cudaGetSymbolAddress((void**)&kb,  g_k);
    cudaGetSymbolAddress((void**)&vb,  g_v);
    cudaGetSymbolAddress((void**)&ab,  g_ao);
    cudaGetSymbolAddress((void**)&wqT, g_wqT);
    cudaGetSymbolAddress((void**)&wkT, g_wkT);
    cudaGetSymbolAddress((void**)&wvT, g_wvT);
    cudaGetSymbolAddress((void**)&woT, g_woT);

    cudaFuncSetAttribute(gemm_tf32, cudaFuncAttributeMaxDynamicSharedMemorySize,
                         GEMM_SMEM);
    cudaFuncSetAttribute(flash_mma, cudaFuncAttributeMaxDynamicSharedMemorySize,
                         FA_SMEM);

    dim3 tb(32, 8);

    // tf32-round inputs
    round_x<<<SEQ * HIDDEN / 1024, 256>>>((const float4*)X, (float4*)xb);
    transposeK<<<dim3(QDIM / 32,  HIDDEN / 32), tb>>>(wq, wqT, QDIM,  HIDDEN);
    transposeK<<<dim3(KVDIM / 32, HIDDEN / 32), tb>>>(wk, wkT, KVDIM, HIDDEN);
    transposeK<<<dim3(KVDIM / 32, HIDDEN / 32), tb>>>(wv, wvT, KVDIM, HIDDEN);
    transposeK<<<dim3(HIDDEN / 32, QDIM / 32),  tb>>>(wo, woT, HIDDEN, QDIM);

    // projections
    gemm_tf32<<<dim3(QDIM / TN, CHUNK / TM), 256, GEMM_SMEM>>>(
        xb + (size_t)CHUNK * HIDDEN, wqT, qb, HIDDEN, HIDDEN, HIDDEN, QDIM, 0);
    gemm_tf32<<<dim3(KVDIM / TN, SEQ / TM), 256, GEMM_SMEM>>>(
        xb, wkT, kb, HIDDEN, HIDDEN, HIDDEN, KVDIM, 0);
    gemm_tf32<<<dim3(KVDIM / TN, SEQ / TM), 256, GEMM_SMEM>>>(
        xb, wvT, vb, HIDDEN, HIDDEN, HIDDEN, KVDIM, 0);

    // RMSNorm (+RoPE), outputs tf32-rounded
    norm_rope<<<dim3(CHUNK, NHEADS), 128>>>(qb, qn, cosb, sinb, NHEADS, CHUNK, 1);
    norm_rope<<<dim3(SEQ, NKVHEADS), 128>>>(kb, kn, cosb, sinb, NKVHEADS, 0, 1);
    norm_rope<<<dim3(SEQ, NKVHEADS), 128>>>(vb, vn, cosb, sinb, NKVHEADS, 0, 0);

    // fused flash attention (S + softcap + mask + softmax + PV)
    flash_mma<<<dim3(CHUNK / FQ, NHEADS), 256, FA_SMEM>>>(qb, kb, vb, ab);

    // output projection
    gemm_tf32<<<dim3(HIDDEN / TN, CHUNK / TM), 256, GEMM_SMEM>>>(
        ab, woT, out, QDIM, QDIM, QDIM, HIDDEN, 0);
}

// round 15
// speedup vs baseline: 1.0765x; 1.0765x over previous
#include <cuda_runtime.h>
#include <cuda_bf16.h>
#include <cstdint>
#include <math.h>

// ---------------------------------------------------------------------------
// Problem constants
// ---------------------------------------------------------------------------
#define SEQ      4096
#define HIDDEN   2048
#define NHEADS   8
#define NKVHEADS 4
#define HDIM     256
#define CHUNK    2048
#define QDIM     (NHEADS * HDIM)    // 2048
#define KVDIM    (NKVHEADS * HDIM)  // 1024

// ---------------------------------------------------------------------------
// Scratch (device globals — no allocation allowed)
// ---------------------------------------------------------------------------
__device__ float g_x  [SEQ * HIDDEN];
__device__ float g_q  [CHUNK * QDIM];
__device__ float g_k  [SEQ * KVDIM];
__device__ float g_v  [SEQ * KVDIM];
__device__ float g_ao [CHUNK * QDIM];
__device__ float g_wqT[HIDDEN * QDIM];
__device__ float g_wkT[HIDDEN * KVDIM];
__device__ float g_wvT[HIDDEN * KVDIM];
__device__ float g_woT[QDIM * HIDDEN];
__device__ float g_vT [NKVHEADS * HDIM * SEQ];
__device__ float g_S  [NHEADS * CHUNK * SEQ];   // 256 MB (P, unnormalized)
__device__ float g_l  [NHEADS * CHUNK];         // row sums

// ---------------------------------------------------------------------------
// PTX helpers (sm_80+-portable only — harness PTX targets plain sm_103,
// so tcgen05/TMEM are unavailable; mma.sync is the tensor path)
// ---------------------------------------------------------------------------
static __device__ __forceinline__ uint32_t s2u(const void* p) {
    uint32_t a;
    asm("{ .reg .u64 t; cvta.to.shared.u64 t, %1; cvt.u32.u64 %0, t; }"
        : "=r"(a) : "l"(p));
    return a;
}

static __device__ __forceinline__ void cp16(uint32_t dst, const void* src) {
    asm volatile("cp.async.cg.shared.global [%0], [%1], 16;"
                 :: "r"(dst), "l"(src) : "memory");
}
#define CP_COMMIT() asm volatile("cp.async.commit_group;" ::: "memory")
#define CP_WAIT1()  asm volatile("cp.async.wait_group 1;" ::: "memory")

// round-to-nearest tf32
static __device__ __forceinline__ float rtf32(float x) {
    uint32_t u = __float_as_uint(x), o;
    asm("cvt.rna.tf32.f32 %0, %1;" : "=r"(o) : "r"(u));
    return __uint_as_float(o);
}

#define MMA_TF32(acc, a0, a1, a2, a3, b0, b1)                                \
    asm volatile(                                                            \
        "mma.sync.aligned.m16n8k8.row.col.f32.tf32.tf32.f32 "                \
        "{%0,%1,%2,%3}, {%4,%5,%6,%7}, {%8,%9}, {%0,%1,%2,%3};"              \
        : "+f"((acc)[0]), "+f"((acc)[1]), "+f"((acc)[2]), "+f"((acc)[3])     \
        : "r"(a0), "r"(a1), "r"(a2), "r"(a3), "r"(b0), "r"(b1))

// ---------------------------------------------------------------------------
// tf32 mma.sync GEMM: C[M,N] = A[M,K](K-major,lda) @ B[N,K](K-major,ldb)^T
// CTA tile 128x256, BK=32, 3-stage cp.async pipeline, 256 threads
// (8 warps, 2x4 grid, 64x64 per warp, m16n8k8 fragments).
// ncap: skip CTA if bn >= ncap0 + by*ncapSlope   (causal tile skip for S)
// kcap: truncate K at kcap0 + by*kcapSlope       (PV truncation)
// mode: 0 = plain store; 1 = S epilogue (softcap+mask+exp, rowsum atomics);
//       2 = PV epilogue (scale by 1/rowsum, tf32-round)
// ---------------------------------------------------------------------------
#define TM 128
#define TN 256
#define TK 32
#define LDSW 36
#define AFL  (128 * LDSW)
#define BFL  (256 * LDSW)
#define STGFL (AFL + BFL)
#define GEMM_SMEM (3 * STGFL * 4)

__global__ __launch_bounds__(256) void gemm_tf32(
    const float* __restrict__ A, const float* __restrict__ B,
    float* __restrict__ C, float* __restrict__ lbuf,
    int K, int lda, int ldb, int ldc,
    long long sAz, long long sBz, long long sCz, int bzShift,
    int ncap0, int ncapSlope, int kcap0, int kcapSlope, int mode)
{
    const int bm = blockIdx.y * TM;
    const int bn = blockIdx.x * TN;
    const int z  = blockIdx.z;
    if (bn >= ncap0 + (int)blockIdx.y * ncapSlope) return;

    long long kcl = (long long)kcap0 + (long long)blockIdx.y * kcapSlope;
    const int Keff = (kcl < (long long)K) ? (int)kcl : K;
    const int kt = Keff / TK;

    A += (size_t)z * sAz + (size_t)bm * lda;
    B += (size_t)(z >> bzShift) * sBz + (size_t)bn * ldb;
    C += (size_t)z * sCz;

    extern __shared__ float smf[];
    const int tid  = threadIdx.x;
    const int w    = tid >> 5, lane = tid & 31;
    const int wm   = w >> 2,   wn   = w & 3;
    const int g    = lane >> 2, t4  = lane & 3;

    const int lr = tid >> 3;
    const int lc = (tid & 7) * 4;

    float acc[4][8][4];
    #pragma unroll
    for (int a1 = 0; a1 < 4; a1++)
        #pragma unroll
        for (int b1 = 0; b1 < 8; b1++)
            #pragma unroll
            for (int c1 = 0; c1 < 4; c1++) acc[a1][b1][c1] = 0.f;

    #define LOAD_STAGE(st, k0)                                                  \
    do {                                                                        \
        float* dA = smf + (st) * STGFL;                                         \
        float* dB = dA + AFL;                                                   \
        _Pragma("unroll")                                                       \
        for (int i = 0; i < 4; i++) {                                           \
            int row = lr + i * 32;                                              \
            cp16(s2u(dA + row * LDSW + lc), A + (size_t)row * lda + (k0) + lc); \
        }                                                                       \
        _Pragma("unroll")                                                       \
        for (int i = 0; i < 8; i++) {                                           \
            int row = lr + i * 32;                                              \
            cp16(s2u(dB + row * LDSW + lc), B + (size_t)row * ldb + (k0) + lc); \
        }                                                                       \
        CP_COMMIT();                                                            \
    } while (0)

    LOAD_STAGE(0, 0);
    if (kt > 1) LOAD_STAGE(1, TK); else CP_COMMIT();

    for (int it = 0; it < kt; it++) {
        CP_WAIT1();
        __syncthreads();

        const int st = it % 3;
        const float* sA = smf + st * STGFL;
        const float* sB = sA + AFL;

        if (it + 2 < kt) { const int s2 = (it + 2) % 3; LOAD_STAGE(s2, (it + 2) * TK); }
        else CP_COMMIT();

        #pragma unroll
        for (int kk = 0; kk < 4; kk++) {
            uint32_t af[4][4], bf[8][2];
            #pragma unroll
            for (int tm = 0; tm < 4; tm++) {
                const float* p = sA + (wm * 64 + tm * 16 + g) * LDSW + kk * 8 + t4;
                af[tm][0] = __float_as_uint(p[0]);
                af[tm][1] = __float_as_uint(p[8 * LDSW]);
                af[tm][2] = __float_as_uint(p[4]);
                af[tm][3] = __float_as_uint(p[8 * LDSW + 4]);
            }
            #pragma unroll
            for (int tn = 0; tn < 8; tn++) {
                const float* p = sB + (wn * 64 + tn * 8 + g) * LDSW + kk * 8 + t4;
                bf[tn][0] = __float_as_uint(p[0]);
                bf[tn][1] = __float_as_uint(p[4]);
            }
            #pragma unroll
            for (int tm = 0; tm < 4; tm++)
                #pragma unroll
                for (int tn = 0; tn < 8; tn++)
                    MMA_TF32(acc[tm][tn], af[tm][0], af[tm][1], af[tm][2],
                             af[tm][3], bf[tn][0], bf[tn][1]);
        }
    }

    if (mode == 1) {
        // ---- S epilogue: softcap + causal mask + shift-free exp + rowsum ----
        float* lrow = lbuf + (size_t)z * CHUNK;
        #pragma unroll
        for (int tm = 0; tm < 4; tm++) {
            const int row0 = bm + wm * 64 + tm * 16 + g;     // q row in head
            const int qp0  = CHUNK + row0;
            const int qp1  = qp0 + 8;
            float sum0 = 0.f, sum1 = 0.f;
            #pragma unroll
            for (int tn = 0; tn < 8; tn++) {
                const int col = bn + wn * 64 + tn * 8 + 2 * t4;
                float p[4];
                #pragma unroll
                for (int c = 0; c < 4; c++) {
                    // softcap: 50*tanh(s/16/50); tanh via e^{2z}
                    float t = __expf(acc[tm][tn][c] * 0.0025f);
                    float l = 50.f * __fdividef(t - 1.f, t + 1.f);
                    const int cc = col + (c & 1);
                    const int qp = (c < 2) ? qp0 : qp1;
                    p[c] = (cc <= qp) ? __expf(l) : 0.f;   // no max-shift needed
                }
                sum0 += p[0] + p[1];
                sum1 += p[2] + p[3];
                *(float2*)&C[(size_t)row0 * ldc + col] =
                    make_float2(rtf32(p[0]), rtf32(p[1]));
                *(float2*)&C[(size_t)(row0 + 8) * ldc + col] =
                    make_float2(rtf32(p[2]), rtf32(p[3]));
            }
            sum0 += __shfl_xor_sync(~0u, sum0, 1);
            sum0 += __shfl_xor_sync(~0u, sum0, 2);
            sum1 += __shfl_xor_sync(~0u, sum1, 1);
            sum1 += __shfl_xor_sync(~0u, sum1, 2);
            if (t4 == 0) {
                atomicAdd(lrow + row0,     sum0);
                atomicAdd(lrow + row0 + 8, sum1);
            }
        }
    } else if (mode == 2) {
        // ---- PV epilogue: normalize by rowsum, tf32-round ----
        const float* lrow = lbuf + (size_t)z * CHUNK;
        #pragma unroll
        for (int tm = 0; tm < 4; tm++) {
            const int row0 = bm + wm * 64 + tm * 16 + g;
            const float linv0 = __fdividef(1.f, lrow[row0]);
            const float linv1 = __fdividef(1.f, lrow[row0 + 8]);
            #pragma unroll
            for (int tn = 0; tn < 8; tn++) {
                const int col = bn + wn * 64 + tn * 8 + 2 * t4;
                *(float2*)&C[(size_t)row0 * ldc + col] =
                    make_float2(rtf32(acc[tm][tn][0] * linv0),
                                rtf32(acc[tm][tn][1] * linv0));
                *(float2*)&C[(size_t)(row0 + 8) * ldc + col] =
                    make_float2(rtf32(acc[tm][tn][2] * linv1),
                                rtf32(acc[tm][tn][3] * linv1));
            }
        }
    } else {
        #pragma unroll
        for (int tm = 0; tm < 4; tm++) {
            const int row0 = bm + wm * 64 + tm * 16 + g;
            #pragma unroll
            for (int tn = 0; tn < 8; tn++) {
                const int col = bn + wn * 64 + tn * 8 + 2 * t4;
                *(float2*)&C[(size_t)row0 * ldc + col] =
                    make_float2(acc[tm][tn][0], acc[tm][tn][1]);
                *(float2*)&C[(size_t)(row0 + 8) * ldc + col] =
                    make_float2(acc[tm][tn][2], acc[tm][tn][3]);
            }
        }
    }
    #undef LOAD_STAGE
}

// ---------------------------------------------------------------------------
// zero the rowsum buffer
// ---------------------------------------------------------------------------
__global__ __launch_bounds__(256) void zero_l(float* __restrict__ l)
{
    l[blockIdx.x * 256 + threadIdx.x] = 0.f;
}

// ---------------------------------------------------------------------------
// 32x32 tiled transpose with tf32 rounding, batched over z
// ---------------------------------------------------------------------------
__global__ __launch_bounds__(256) void transposeK(
    const float* __restrict__ in, float* __restrict__ out,
    int ldin, int ldout, long long sInZ, long long sOutZ)
{
    __shared__ float t[32][33];
    const int z = blockIdx.z;
    in  += (size_t)z * sInZ;
    out += (size_t)z * sOutZ;
    const int c0 = blockIdx.x * 32, r0 = blockIdx.y * 32;
    const int tx = threadIdx.x, ty = threadIdx.y;
    #pragma unroll
    for (int i = ty; i < 32; i += 8)
        t[i][tx] = in[(size_t)(r0 + i) * ldin + c0 + tx];
    __syncthreads();
    #pragma unroll
    for (int i = ty; i < 32; i += 8)
        out[(size_t)(c0 + i) * ldout + r0 + tx] = rtf32(t[tx][i]);
}

// ---------------------------------------------------------------------------
// Elementwise tf32 round
// ---------------------------------------------------------------------------
__global__ __launch_bounds__(256) void round_x(
    const float4* __restrict__ in, float4* __restrict__ out)
{
    int i = blockIdx.x * 256 + threadIdx.x;
    float4 v = in[i];
    v.x = rtf32(v.x); v.y = rtf32(v.y); v.z = rtf32(v.z); v.w = rtf32(v.w);
    out[i] = v;
}

// ---------------------------------------------------------------------------
// RMSNorm (+ optional RoPE), head_dim = 256, in place, tf32-rounded output
// ---------------------------------------------------------------------------
__global__ __launch_bounds__(128) void norm_rope(
    float* __restrict__ buf, const float* __restrict__ w,
    const float* __restrict__ cosb, const float* __restrict__ sinb,
    int nheads, int pos_off, int use_rope)
{
    const int tok = blockIdx.x;
    const int h   = blockIdx.y;
    float* x = buf + ((size_t)tok * nheads + h) * HDIM;
    const int i = threadIdx.x;

    float x1 = x[i];
    float x2 = x[i + 128];
    float ss = x1 * x1 + x2 * x2;
    #pragma unroll
    for (int off = 16; off > 0; off >>= 1)
        ss += __shfl_xor_sync(0xffffffffu, ss, off);
    __shared__ float wsum[4];
    if ((i & 31) == 0) wsum[i >> 5] = ss;
    __syncthreads();
    float tot = wsum[0] + wsum[1] + wsum[2] + wsum[3];

    float scale = rsqrtf(tot * (1.0f / 256.0f) + 1e-6f);
    float xn1 = x1 * scale * (1.0f + w[i]);
    float xn2 = x2 * scale * (1.0f + w[i + 128]);

    if (use_rope) {
        const size_t p = (size_t)(pos_off + tok) * HDIM;
        float c1 = cosb[p + i],       s1 = sinb[p + i];
        float c2 = cosb[p + i + 128], s2 = sinb[p + i + 128];
        x[i]       = rtf32(xn1 * c1 - xn2 * s1);
        x[i + 128] = rtf32(xn2 * c2 + xn1 * s2);
    } else {
        x[i]       = rtf32(xn1);
        x[i + 128] = rtf32(xn2);
    }
}

// ---------------------------------------------------------------------------
// Launch
// ---------------------------------------------------------------------------
extern "C" void kernel_launch(void* const* d_in, const int* in_sizes, int n_in,
                              void* d_out, int out_size)
{
    const float* X    = (const float*)d_in[0];
    const float* cosb = (const float*)d_in[1];
    const float* sinb = (const float*)d_in[2];
    const float* wq   = (const float*)d_in[4];
    const float* wk   = (const float*)d_in[5];
    const float* wv   = (const float*)d_in[6];
    const float* wo   = (const float*)d_in[7];
    const float* qn   = (const float*)d_in[8];
    const float* kn   = (const float*)d_in[9];
    const float* vn   = (const float*)d_in[10];
    float* out = (float*)d_out;

    float *xb, *qb, *kb, *vb, *ab, *wqT, *wkT, *wvT, *woT, *vT, *Sb, *lb;
    cudaGetSymbolAddress((void**)&xb,  g_x);
    cudaGetSymbolAddress((void**)&qb,  g_q);
    cudaGetSymbolAddress((void**)&kb,  g_k);
    cudaGetSymbolAddress((void**)&vb,  g_v);
    cudaGetSymbolAddress((void**)&ab,  g_ao);
    cudaGetSymbolAddress((void**)&wqT, g_wqT);
    cudaGetSymbolAddress((void**)&wkT, g_wkT);
    cudaGetSymbolAddress((void**)&wvT, g_wvT);
    cudaGetSymbolAddress((void**)&woT, g_woT);
    cudaGetSymbolAddress((void**)&vT,  g_vT);
    cudaGetSymbolAddress((void**)&Sb,  g_S);
    cudaGetSymbolAddress((void**)&lb,  g_l);

    cudaFuncSetAttribute(gemm_tf32, cudaFuncAttributeMaxDynamicSharedMemorySize,
                         GEMM_SMEM);

    const int BIG = 1 << 30;
    dim3 tb(32, 8);

    // tf32-round inputs; zero rowsums
    round_x<<<SEQ * HIDDEN / 1024, 256>>>((const float4*)X, (float4*)xb);
    zero_l<<<NHEADS * CHUNK / 256, 256>>>(lb);
    transposeK<<<dim3(QDIM / 32,  HIDDEN / 32), tb>>>(wq, wqT, QDIM,  HIDDEN, 0, 0);
    transposeK<<<dim3(KVDIM / 32, HIDDEN / 32), tb>>>(wk, wkT, KVDIM, HIDDEN, 0, 0);
    transposeK<<<dim3(KVDIM / 32, HIDDEN / 32), tb>>>(wv, wvT, KVDIM, HIDDEN, 0, 0);
    transposeK<<<dim3(HIDDEN / 32, QDIM / 32),  tb>>>(wo, woT, HIDDEN, QDIM,  0, 0);

    // projections
    gemm_tf32<<<dim3(QDIM / TN, CHUNK / TM, 1), 256, GEMM_SMEM>>>(
        xb + (size_t)CHUNK * HIDDEN, wqT, qb, lb,
        HIDDEN, HIDDEN, HIDDEN, QDIM, 0, 0, 0, 0, BIG, 0, BIG, 0, 0);
    gemm_tf32<<<dim3(KVDIM / TN, SEQ / TM, 1), 256, GEMM_SMEM>>>(
        xb, wkT, kb, lb, HIDDEN, HIDDEN, HIDDEN, KVDIM, 0, 0, 0, 0, BIG, 0, BIG, 0, 0);
    gemm_tf32<<<dim3(KVDIM / TN, SEQ / TM, 1), 256, GEMM_SMEM>>>(
        xb, wvT, vb, lb, HIDDEN, HIDDEN, HIDDEN, KVDIM, 0, 0, 0, 0, BIG, 0, BIG, 0, 0);

    // RMSNorm (+RoPE), outputs tf32-rounded
    norm_rope<<<dim3(CHUNK, NHEADS), 128>>>(qb, qn, cosb, sinb, NHEADS, CHUNK, 1);
    norm_rope<<<dim3(SEQ, NKVHEADS), 128>>>(kb, kn, cosb, sinb, NKVHEADS, 0, 1);
    norm_rope<<<dim3(SEQ, NKVHEADS), 128>>>(vb, vn, cosb, sinb, NKVHEADS, 0, 0);

    // V^T per kv head: [256, 4096]
    transposeK<<<dim3(HDIM / 32, SEQ / 32, NKVHEADS), tb>>>(
        vb, vT, KVDIM, SEQ, HDIM, (long long)HDIM * SEQ);

    // S = Q @ K^T with fused softcap+mask+exp+rowsum epilogue (mode 1)
    gemm_tf32<<<dim3(SEQ / TN, CHUNK / TM, NHEADS), 256, GEMM_SMEM>>>(
        qb, kb, Sb, lb,
        HDIM, QDIM, KVDIM, SEQ,
        (long long)HDIM, (long long)HDIM, (long long)CHUNK * SEQ, 1,
        CHUNK + TM, TM, BIG, 0, 1);

    // O = P @ V with normalization epilogue (mode 2); K truncated per M-tile
    gemm_tf32<<<dim3(HDIM / TN, CHUNK / TM, NHEADS), 256, GEMM_SMEM>>>(
        Sb, vT, ab, lb,
        SEQ, SEQ, SEQ, QDIM,
        (long long)CHUNK * SEQ, (long long)HDIM * SEQ, (long long)HDIM, 1,
        BIG, 0, CHUNK + TM, TM, 2);

    // output projection
    gemm_tf32<<<dim3(HIDDEN / TN, CHUNK / TM, 1), 256, GEMM_SMEM>>>(
        ab, woT, out, lb, QDIM, QDIM, QDIM, HIDDEN, 0, 0, 0, 0, BIG, 0, BIG, 0, 0);
}